// round 11
// baseline (speedup 1.0000x reference)
#include <cuda_runtime.h>
#include <cstdint>

#define NB 256
#define NT 512
#define NI 64
#define ND 512
#define NO 128

// 256 MB scratch for e = tanh(x @ W_in^T + b_in), layout [B*T][D]
__device__ float g_e[(size_t)NB * NT * ND];

// R1's verified tanh: tanh(x) = 1 - 2t/(1+t), t = e^{-2x}. abs err ~1e-7.
__device__ __forceinline__ float tanh_fast(float x) {
    x = fminf(20.0f, fmaxf(-20.0f, x));
    float t = __expf(-2.0f * x);
    return 1.0f - __fdividef(2.0f * t, 1.0f + t);
}

// Packed dual-fp32 FMA (B300 f32x2 pipe): d = a*b + d on 2 lanes.
__device__ __forceinline__ void ffma2(unsigned long long& d,
                                      unsigned long long a,
                                      unsigned long long b) {
    asm("fma.rn.f32x2 %0, %1, %2, %0;" : "+l"(d) : "l"(a), "l"(b));
}

__device__ __forceinline__ unsigned long long pack2(float v) {
    unsigned long long r;
    asm("mov.b64 %0, {%1, %1};" : "=l"(r) : "f"(v));
    return r;
}

__device__ __forceinline__ float2 unpack2(unsigned long long p) {
    float2 r;
    asm("mov.b64 {%0, %1}, %2;" : "=f"(r.x), "=f"(r.y) : "l"(p));
    return r;
}

// ---------------------------------------------------------------------------
// Kernel A: e[m][n] = tanh( sum_k x[m][k] * W_in[n][k] + b_in[n] )
// Block tile: 64M x 256N, full K=64 in smem (k-major). 256 threads.
// Thread tile 8M x 8N (acc as 32 packed f32x2). 2 blocks/SM (80 KB smem each).
// ---------------------------------------------------------------------------
__global__ __launch_bounds__(256, 2)
void embed_kernel(const float* __restrict__ xg,
                  const float* __restrict__ Wg,
                  const float* __restrict__ bg) {
    extern __shared__ float sm[];
    float* Ws = sm;             // [64][256]  Ws[k*256 + j] = W_in[n0+j][k]
    float* xs = sm + NI * 256;  // [64][64]   xs[k*64 + m]  = x[m0+m][k]
    const int tid = threadIdx.x;
    const int m0 = (blockIdx.x >> 1) * 64;
    const int n0 = (blockIdx.x & 1) * 256;

    // Load W rows n0+tid (64 floats each), transposed into k-major smem.
    {
        const float4* wr = reinterpret_cast<const float4*>(Wg + (size_t)(n0 + tid) * NI);
        #pragma unroll
        for (int kk = 0; kk < 16; kk++) {
            float4 v = wr[kk];
            Ws[(4 * kk + 0) * 256 + tid] = v.x;
            Ws[(4 * kk + 1) * 256 + tid] = v.y;
            Ws[(4 * kk + 2) * 256 + tid] = v.z;
            Ws[(4 * kk + 3) * 256 + tid] = v.w;
        }
    }
    // Load x tile transposed: 4 threads per row, 4 float4 each.
    {
        const int r = tid >> 2;
        const int c = tid & 3;
        const float4* xr = reinterpret_cast<const float4*>(xg + (size_t)(m0 + r) * NI);
        #pragma unroll
        for (int q = 0; q < 4; q++) {
            int kk = c * 4 + q;
            float4 v = xr[kk];
            xs[(4 * kk + 0) * 64 + r] = v.x;
            xs[(4 * kk + 1) * 64 + r] = v.y;
            xs[(4 * kk + 2) * 64 + r] = v.z;
            xs[(4 * kk + 3) * 64 + r] = v.w;
        }
    }
    __syncthreads();

    const int ty = tid >> 5;  // 0..7  -> rows m = ty*8 + j (warp-uniform)
    const int tx = tid & 31;  // cols  n = n0 + tx*4 (+128)

    unsigned long long acc[8][4];
    #pragma unroll
    for (int m = 0; m < 8; m++)
        #pragma unroll
        for (int p = 0; p < 4; p++) acc[m][p] = 0ULL;

    #pragma unroll 8
    for (int k = 0; k < NI; k++) {
        // x: warp-uniform broadcast loads (8 rows)
        float4 xa = *reinterpret_cast<const float4*>(&xs[k * 64 + ty * 8]);
        float4 xb = *reinterpret_cast<const float4*>(&xs[k * 64 + ty * 8 + 4]);
        // W: two conflict-free 16B LDS.128 -> four packed f32x2 operands
        ulonglong2 w0 = *reinterpret_cast<const ulonglong2*>(&Ws[k * 256 + tx * 4]);
        ulonglong2 w1 = *reinterpret_cast<const ulonglong2*>(&Ws[k * 256 + tx * 4 + 128]);
        unsigned long long xp[8];
        xp[0] = pack2(xa.x); xp[1] = pack2(xa.y); xp[2] = pack2(xa.z); xp[3] = pack2(xa.w);
        xp[4] = pack2(xb.x); xp[5] = pack2(xb.y); xp[6] = pack2(xb.z); xp[7] = pack2(xb.w);
        #pragma unroll
        for (int m = 0; m < 8; m++) {
            ffma2(acc[m][0], xp[m], w0.x);
            ffma2(acc[m][1], xp[m], w0.y);
            ffma2(acc[m][2], xp[m], w1.x);
            ffma2(acc[m][3], xp[m], w1.y);
        }
    }

    const float4 bv0 = *reinterpret_cast<const float4*>(bg + n0 + tx * 4);
    const float4 bv1 = *reinterpret_cast<const float4*>(bg + n0 + tx * 4 + 128);
    #pragma unroll
    for (int m = 0; m < 8; m++) {
        float* orow = &g_e[(size_t)(m0 + ty * 8 + m) * ND + n0 + tx * 4];
        float2 a0 = unpack2(acc[m][0]);
        float2 a1 = unpack2(acc[m][1]);
        float2 a2 = unpack2(acc[m][2]);
        float2 a3 = unpack2(acc[m][3]);
        float4 r0, r1;
        r0.x = tanh_fast(a0.x + bv0.x);
        r0.y = tanh_fast(a0.y + bv0.y);
        r0.z = tanh_fast(a1.x + bv0.z);
        r0.w = tanh_fast(a1.y + bv0.w);
        r1.x = tanh_fast(a2.x + bv1.x);
        r1.y = tanh_fast(a2.y + bv1.y);
        r1.z = tanh_fast(a3.x + bv1.z);
        r1.w = tanh_fast(a3.y + bv1.w);
        *reinterpret_cast<float4*>(orow) = r0;
        *reinterpret_cast<float4*>(orow + 128) = r1;
    }
}

// ---------------------------------------------------------------------------
// Kernel B: sequential recurrence + LayerNorm + fused logits epilogue.
// One block per batch row. 128 threads x 4 contiguous d's in registers.
// e_t prefetched 3 steps ahead as register float4. One __syncthreads per step
// (parity-double-buffered cross-warp reduce).
// ---------------------------------------------------------------------------
__global__ __launch_bounds__(128, 2)
void recur_kernel(const float* __restrict__ gamma, const float* __restrict__ beta,
                  const float* __restrict__ Wout, const float* __restrict__ bout,
                  const float* __restrict__ csp, float* __restrict__ outp) {
    __shared__ __align__(16) float2 red[2][4];   // per-warp (sum, sumsq), parity-buffered
    __shared__ __align__(16) float hs[ND];       // final h for logits epilogue
    const int tid = threadIdx.x;
    const int b = blockIdx.x;
    const int d0 = tid * 4;
    const int wid = tid >> 5;
    const int lane = tid & 31;

    const float scale = __fdividef(1.0f, 1.0f + __expf(-csp[0]));  // sigmoid (R1 form)
    const float4 g4 = *reinterpret_cast<const float4*>(gamma + d0);
    const float4 be4 = *reinterpret_cast<const float4*>(beta + d0);

    float s0 = 0.f, s1 = 0.f, s2 = 0.f, s3 = 0.f;
    float h0 = 0.f, h1 = 0.f, h2 = 0.f, h3 = 0.f;

    const float4* ep = reinterpret_cast<const float4*>(g_e + (size_t)b * NT * ND) + tid;
    // 3-deep register prefetch ring (per-thread private 16B/step)
    float4 e_c  = __ldg(ep);
    float4 e_n1 = __ldg(ep + 128);
    float4 e_n2 = __ldg(ep + 256);

    for (int t = 0; t < NT; t++) {
        float4 e4 = e_c;
        e_c = e_n1;
        e_n1 = e_n2;
        if (t + 3 < NT) e_n2 = __ldg(ep + (size_t)(t + 3) * 128);

        s0 = tanh_fast(fmaf(scale, s0, e4.x) + h0);
        s1 = tanh_fast(fmaf(scale, s1, e4.y) + h1);
        s2 = tanh_fast(fmaf(scale, s2, e4.z) + h2);
        s3 = tanh_fast(fmaf(scale, s3, e4.w) + h3);

        float sum = (s0 + s1) + (s2 + s3);
        float ssq = fmaf(s0, s0, s1 * s1) + fmaf(s2, s2, s3 * s3);
        #pragma unroll
        for (int m = 16; m >= 1; m >>= 1) {
            sum += __shfl_xor_sync(0xffffffffu, sum, m);
            ssq += __shfl_xor_sync(0xffffffffu, ssq, m);
        }
        if (lane == 0) red[t & 1][wid] = make_float2(sum, ssq);
        __syncthreads();
        float4 ra = *reinterpret_cast<const float4*>(&red[t & 1][0]);
        float4 rb = *reinterpret_cast<const float4*>(&red[t & 1][2]);
        float tsum = (ra.x + ra.z) + (rb.x + rb.z);
        float tssq = (ra.y + ra.w) + (rb.y + rb.w);
        float mean = tsum * (1.0f / ND);
        float var = fmaf(mean, -mean, tssq * (1.0f / ND));
        float rs = rsqrtf(var + 1e-5f);
        h0 = fmaf((s0 - mean) * rs, g4.x, be4.x);
        h1 = fmaf((s1 - mean) * rs, g4.y, be4.y);
        h2 = fmaf((s2 - mean) * rs, g4.z, be4.z);
        h3 = fmaf((s3 - mean) * rs, g4.w, be4.w);
    }

    // ---- fused logits: out[b][o] = b_out[o] + sum_d h[d] * W_out[o][d] ----
    *reinterpret_cast<float4*>(&hs[d0]) = make_float4(h0, h1, h2, h3);
    __syncthreads();

    float acc = bout[tid];  // blockDim == NO == 128, thread owns output o = tid
    const float4* wr = reinterpret_cast<const float4*>(Wout + (size_t)tid * ND);
    const float4* hv = reinterpret_cast<const float4*>(&hs[0]);
    #pragma unroll 8
    for (int q = 0; q < ND / 4; q++) {
        float4 w = __ldg(&wr[q]);
        float4 h = hv[q];
        acc = fmaf(w.x, h.x, fmaf(w.y, h.y, fmaf(w.z, h.z, fmaf(w.w, h.w, acc))));
    }
    outp[b * NO + tid] = acc;
}

// ---------------------------------------------------------------------------
extern "C" void kernel_launch(void* const* d_in, const int* in_sizes, int n_in,
                              void* d_out, int out_size) {
    const float* x     = (const float*)d_in[0];
    const float* Win   = (const float*)d_in[1];
    const float* bin   = (const float*)d_in[2];
    const float* gamma = (const float*)d_in[3];
    const float* beta  = (const float*)d_in[4];
    const float* Wout  = (const float*)d_in[5];
    const float* bout  = (const float*)d_in[6];
    const float* cs    = (const float*)d_in[7];
    float* out = (float*)d_out;

    const int smem = (NI * 256 + NI * 64) * (int)sizeof(float);  // 81920 B
    cudaFuncSetAttribute(embed_kernel, cudaFuncAttributeMaxDynamicSharedMemorySize, smem);
    embed_kernel<<<(NB * NT / 64) * 2, 256, smem>>>(x, Win, bin);
    recur_kernel<<<NB, 128>>>(gamma, beta, Wout, bout, cs, out);
}

// round 12
// speedup vs baseline: 1.0688x; 1.0688x over previous
#include <cuda_runtime.h>
#include <cstdint>

#define NB 256
#define NT 512
#define NI 64
#define ND 512
#define NO 128

// 256 MB scratch for e = tanh(x @ W_in^T + b_in), layout [B*T][D]
__device__ float g_e[(size_t)NB * NT * ND];

// Verified tanh: tanh(x) = 1 - 2t/(1+t), t = e^{-2x}. __fdividef is
// Newton-refined (~2 ulp) — raw rcp.approx (2^-14) is NOT acceptable here
// (proved by R7 vs R11: 7.9e-3 vs 1.2e-4 final rel_err).
__device__ __forceinline__ float tanh_fast(float x) {
    x = fminf(20.0f, fmaxf(-20.0f, x));
    float t = __expf(-2.0f * x);
    return 1.0f - __fdividef(2.0f * t, 1.0f + t);
}

// Packed dual-fp32 FMA (B300 f32x2 pipe): d = a*b + d on 2 lanes.
__device__ __forceinline__ void ffma2(unsigned long long& d,
                                      unsigned long long a,
                                      unsigned long long b) {
    asm("fma.rn.f32x2 %0, %1, %2, %0;" : "+l"(d) : "l"(a), "l"(b));
}

__device__ __forceinline__ unsigned long long pack2(float v) {
    unsigned long long r;
    asm("mov.b64 %0, {%1, %1};" : "=l"(r) : "f"(v));
    return r;
}

__device__ __forceinline__ float2 unpack2(unsigned long long p) {
    float2 r;
    asm("mov.b64 {%0, %1}, %2;" : "=f"(r.x), "=f"(r.y) : "l"(p));
    return r;
}

// ---------------------------------------------------------------------------
// Kernel A (unchanged from R11, measured ~220 us, scalar-FMA roofline):
// e[m][n] = tanh( sum_k x[m][k] * W_in[n][k] + b_in[n] )
// Block tile: 64M x 256N, full K=64 in smem (k-major). 256 threads.
// ---------------------------------------------------------------------------
__global__ __launch_bounds__(256, 2)
void embed_kernel(const float* __restrict__ xg,
                  const float* __restrict__ Wg,
                  const float* __restrict__ bg) {
    extern __shared__ float sm[];
    float* Ws = sm;             // [64][256]  Ws[k*256 + j] = W_in[n0+j][k]
    float* xs = sm + NI * 256;  // [64][64]   xs[k*64 + m]  = x[m0+m][k]
    const int tid = threadIdx.x;
    const int m0 = (blockIdx.x >> 1) * 64;
    const int n0 = (blockIdx.x & 1) * 256;

    {
        const float4* wr = reinterpret_cast<const float4*>(Wg + (size_t)(n0 + tid) * NI);
        #pragma unroll
        for (int kk = 0; kk < 16; kk++) {
            float4 v = wr[kk];
            Ws[(4 * kk + 0) * 256 + tid] = v.x;
            Ws[(4 * kk + 1) * 256 + tid] = v.y;
            Ws[(4 * kk + 2) * 256 + tid] = v.z;
            Ws[(4 * kk + 3) * 256 + tid] = v.w;
        }
    }
    {
        const int r = tid >> 2;
        const int c = tid & 3;
        const float4* xr = reinterpret_cast<const float4*>(xg + (size_t)(m0 + r) * NI);
        #pragma unroll
        for (int q = 0; q < 4; q++) {
            int kk = c * 4 + q;
            float4 v = xr[kk];
            xs[(4 * kk + 0) * 64 + r] = v.x;
            xs[(4 * kk + 1) * 64 + r] = v.y;
            xs[(4 * kk + 2) * 64 + r] = v.z;
            xs[(4 * kk + 3) * 64 + r] = v.w;
        }
    }
    __syncthreads();

    const int ty = tid >> 5;
    const int tx = tid & 31;

    unsigned long long acc[8][4];
    #pragma unroll
    for (int m = 0; m < 8; m++)
        #pragma unroll
        for (int p = 0; p < 4; p++) acc[m][p] = 0ULL;

    #pragma unroll 8
    for (int k = 0; k < NI; k++) {
        float4 xa = *reinterpret_cast<const float4*>(&xs[k * 64 + ty * 8]);
        float4 xb = *reinterpret_cast<const float4*>(&xs[k * 64 + ty * 8 + 4]);
        ulonglong2 w0 = *reinterpret_cast<const ulonglong2*>(&Ws[k * 256 + tx * 4]);
        ulonglong2 w1 = *reinterpret_cast<const ulonglong2*>(&Ws[k * 256 + tx * 4 + 128]);
        unsigned long long xp[8];
        xp[0] = pack2(xa.x); xp[1] = pack2(xa.y); xp[2] = pack2(xa.z); xp[3] = pack2(xa.w);
        xp[4] = pack2(xb.x); xp[5] = pack2(xb.y); xp[6] = pack2(xb.z); xp[7] = pack2(xb.w);
        #pragma unroll
        for (int m = 0; m < 8; m++) {
            ffma2(acc[m][0], xp[m], w0.x);
            ffma2(acc[m][1], xp[m], w0.y);
            ffma2(acc[m][2], xp[m], w1.x);
            ffma2(acc[m][3], xp[m], w1.y);
        }
    }

    const float4 bv0 = *reinterpret_cast<const float4*>(bg + n0 + tx * 4);
    const float4 bv1 = *reinterpret_cast<const float4*>(bg + n0 + tx * 4 + 128);
    #pragma unroll
    for (int m = 0; m < 8; m++) {
        float* orow = &g_e[(size_t)(m0 + ty * 8 + m) * ND + n0 + tx * 4];
        float2 a0 = unpack2(acc[m][0]);
        float2 a1 = unpack2(acc[m][1]);
        float2 a2 = unpack2(acc[m][2]);
        float2 a3 = unpack2(acc[m][3]);
        float4 r0, r1;
        r0.x = tanh_fast(a0.x + bv0.x);
        r0.y = tanh_fast(a0.y + bv0.y);
        r0.z = tanh_fast(a1.x + bv0.z);
        r0.w = tanh_fast(a1.y + bv0.w);
        r1.x = tanh_fast(a2.x + bv1.x);
        r1.y = tanh_fast(a2.y + bv1.y);
        r1.z = tanh_fast(a3.x + bv1.z);
        r1.w = tanh_fast(a3.y + bv1.w);
        *reinterpret_cast<float4*>(orow) = r0;
        *reinterpret_cast<float4*>(orow + 128) = r1;
    }
}

// ---------------------------------------------------------------------------
// Kernel B: sequential recurrence + LayerNorm + fused logits epilogue.
// One block per batch row. 128 threads x 4 contiguous d's in registers.
// FIX vs R11: prefetch buffer is a 4-slot array with #pragma unroll 4 and t&3
// indexing — no register shift chain across the backedge, so the LDG issued at
// step t is consumed at step t+3 (true depth-3 latency cover), instead of the
// rolled-loop shift (e_n1 = e_n2) that serialized on the previous iteration's
// load and made R11's recur 276 us.
// ---------------------------------------------------------------------------
__global__ __launch_bounds__(128, 2)
void recur_kernel(const float* __restrict__ gamma, const float* __restrict__ beta,
                  const float* __restrict__ Wout, const float* __restrict__ bout,
                  const float* __restrict__ csp, float* __restrict__ outp) {
    __shared__ __align__(16) float2 red[2][4];   // per-warp (sum, sumsq), parity-buffered
    __shared__ __align__(16) float hs[ND];       // final h for logits epilogue
    const int tid = threadIdx.x;
    const int b = blockIdx.x;
    const int d0 = tid * 4;
    const int wid = tid >> 5;
    const int lane = tid & 31;

    const float scale = __fdividef(1.0f, 1.0f + __expf(-csp[0]));  // sigmoid
    const float4 g4 = *reinterpret_cast<const float4*>(gamma + d0);
    const float4 be4 = *reinterpret_cast<const float4*>(beta + d0);

    float s0 = 0.f, s1 = 0.f, s2 = 0.f, s3 = 0.f;
    float h0 = 0.f, h1 = 0.f, h2 = 0.f, h3 = 0.f;

    const float4* ep = reinterpret_cast<const float4*>(g_e + (size_t)b * NT * ND) + tid;

    float4 ebuf[4];
    ebuf[0] = __ldg(ep);
    ebuf[1] = __ldg(ep + 128);
    ebuf[2] = __ldg(ep + 256);

    #pragma unroll 4
    for (int t = 0; t < NT; t++) {
        const float4 e4 = ebuf[t & 3];
        // Prefetch step t+3 into the slot just vacated. Clamp keeps the tail
        // in-bounds (loads a valid row whose value is never consumed).
        const int tp = (t + 3 < NT) ? (t + 3) : (NT - 1);
        ebuf[(t + 3) & 3] = __ldg(ep + (size_t)tp * 128);

        s0 = tanh_fast(fmaf(scale, s0, e4.x) + h0);
        s1 = tanh_fast(fmaf(scale, s1, e4.y) + h1);
        s2 = tanh_fast(fmaf(scale, s2, e4.z) + h2);
        s3 = tanh_fast(fmaf(scale, s3, e4.w) + h3);

        float sum = (s0 + s1) + (s2 + s3);
        float ssq = fmaf(s0, s0, s1 * s1) + fmaf(s2, s2, s3 * s3);
        #pragma unroll
        for (int m = 16; m >= 1; m >>= 1) {
            sum += __shfl_xor_sync(0xffffffffu, sum, m);
            ssq += __shfl_xor_sync(0xffffffffu, ssq, m);
        }
        if (lane == 0) red[t & 1][wid] = make_float2(sum, ssq);
        __syncthreads();
        float4 ra = *reinterpret_cast<const float4*>(&red[t & 1][0]);
        float4 rb = *reinterpret_cast<const float4*>(&red[t & 1][2]);
        float tsum = (ra.x + ra.z) + (rb.x + rb.z);
        float tssq = (ra.y + ra.w) + (rb.y + rb.w);
        float mean = tsum * (1.0f / ND);
        float var = fmaf(mean, -mean, tssq * (1.0f / ND));
        float rs = rsqrtf(var + 1e-5f);
        h0 = fmaf((s0 - mean) * rs, g4.x, be4.x);
        h1 = fmaf((s1 - mean) * rs, g4.y, be4.y);
        h2 = fmaf((s2 - mean) * rs, g4.z, be4.z);
        h3 = fmaf((s3 - mean) * rs, g4.w, be4.w);
    }

    // ---- fused logits: out[b][o] = b_out[o] + sum_d h[d] * W_out[o][d] ----
    *reinterpret_cast<float4*>(&hs[d0]) = make_float4(h0, h1, h2, h3);
    __syncthreads();

    float acc = bout[tid];  // blockDim == NO == 128, thread owns output o = tid
    const float4* wr = reinterpret_cast<const float4*>(Wout + (size_t)tid * ND);
    const float4* hv = reinterpret_cast<const float4*>(&hs[0]);
    #pragma unroll 8
    for (int q = 0; q < ND / 4; q++) {
        float4 w = __ldg(&wr[q]);
        float4 h = hv[q];
        acc = fmaf(w.x, h.x, fmaf(w.y, h.y, fmaf(w.z, h.z, fmaf(w.w, h.w, acc))));
    }
    outp[b * NO + tid] = acc;
}

// ---------------------------------------------------------------------------
extern "C" void kernel_launch(void* const* d_in, const int* in_sizes, int n_in,
                              void* d_out, int out_size) {
    const float* x     = (const float*)d_in[0];
    const float* Win   = (const float*)d_in[1];
    const float* bin   = (const float*)d_in[2];
    const float* gamma = (const float*)d_in[3];
    const float* beta  = (const float*)d_in[4];
    const float* Wout  = (const float*)d_in[5];
    const float* bout  = (const float*)d_in[6];
    const float* cs    = (const float*)d_in[7];
    float* out = (float*)d_out;

    const int smem = (NI * 256 + NI * 64) * (int)sizeof(float);  // 81920 B
    cudaFuncSetAttribute(embed_kernel, cudaFuncAttributeMaxDynamicSharedMemorySize, smem);
    embed_kernel<<<(NB * NT / 64) * 2, 256, smem>>>(x, Win, bin);
    recur_kernel<<<NB, 128>>>(gamma, beta, Wout, bout, cs, out);
}

// round 13
// speedup vs baseline: 1.2923x; 1.2092x over previous
#include <cuda_runtime.h>
#include <cstdint>

#define NB 256
#define NT 512
#define NI 64
#define ND 512
#define NO 128

// 256 MB scratch for e = tanh(x @ W_in^T + b_in), layout [B*T][D]
__device__ float g_e[(size_t)NB * NT * ND];

// Verified tanh: tanh(x) = 1 - 2t/(1+t), t = e^{-2x}. __fdividef is
// Newton-refined (~2 ulp) — raw rcp.approx (2^-14) is NOT acceptable
// (R7 vs R11: 7.9e-3 vs 1.2e-4 final rel_err).
__device__ __forceinline__ float tanh_fast(float x) {
    x = fminf(20.0f, fmaxf(-20.0f, x));
    float t = __expf(-2.0f * x);
    return 1.0f - __fdividef(2.0f * t, 1.0f + t);
}

// Packed dual-fp32 FMA (B300 f32x2 pipe): d = a*b + d on 2 lanes.
__device__ __forceinline__ void ffma2(unsigned long long& d,
                                      unsigned long long a,
                                      unsigned long long b) {
    asm("fma.rn.f32x2 %0, %1, %2, %0;" : "+l"(d) : "l"(a), "l"(b));
}

__device__ __forceinline__ unsigned long long pack2(float v) {
    unsigned long long r;
    asm("mov.b64 %0, {%1, %1};" : "=l"(r) : "f"(v));
    return r;
}

__device__ __forceinline__ float2 unpack2(unsigned long long p) {
    float2 r;
    asm("mov.b64 {%0, %1}, %2;" : "=f"(r.x), "=f"(r.y) : "l"(p));
    return r;
}

// ---------------------------------------------------------------------------
// Kernel A (R11/R12 version, measured ~219 us twice):
// e[m][n] = tanh( sum_k x[m][k] * W_in[n][k] + b_in[n] )
// Block tile: 64M x 256N, full K=64 in smem (k-major). 256 threads.
// ---------------------------------------------------------------------------
__global__ __launch_bounds__(256, 2)
void embed_kernel(const float* __restrict__ xg,
                  const float* __restrict__ Wg,
                  const float* __restrict__ bg) {
    extern __shared__ float sm[];
    float* Ws = sm;             // [64][256]  Ws[k*256 + j] = W_in[n0+j][k]
    float* xs = sm + NI * 256;  // [64][64]   xs[k*64 + m]  = x[m0+m][k]
    const int tid = threadIdx.x;
    const int m0 = (blockIdx.x >> 1) * 64;
    const int n0 = (blockIdx.x & 1) * 256;

    {
        const float4* wr = reinterpret_cast<const float4*>(Wg + (size_t)(n0 + tid) * NI);
        #pragma unroll
        for (int kk = 0; kk < 16; kk++) {
            float4 v = wr[kk];
            Ws[(4 * kk + 0) * 256 + tid] = v.x;
            Ws[(4 * kk + 1) * 256 + tid] = v.y;
            Ws[(4 * kk + 2) * 256 + tid] = v.z;
            Ws[(4 * kk + 3) * 256 + tid] = v.w;
        }
    }
    {
        const int r = tid >> 2;
        const int c = tid & 3;
        const float4* xr = reinterpret_cast<const float4*>(xg + (size_t)(m0 + r) * NI);
        #pragma unroll
        for (int q = 0; q < 4; q++) {
            int kk = c * 4 + q;
            float4 v = xr[kk];
            xs[(4 * kk + 0) * 64 + r] = v.x;
            xs[(4 * kk + 1) * 64 + r] = v.y;
            xs[(4 * kk + 2) * 64 + r] = v.z;
            xs[(4 * kk + 3) * 64 + r] = v.w;
        }
    }
    __syncthreads();

    const int ty = tid >> 5;
    const int tx = tid & 31;

    unsigned long long acc[8][4];
    #pragma unroll
    for (int m = 0; m < 8; m++)
        #pragma unroll
        for (int p = 0; p < 4; p++) acc[m][p] = 0ULL;

    #pragma unroll 8
    for (int k = 0; k < NI; k++) {
        float4 xa = *reinterpret_cast<const float4*>(&xs[k * 64 + ty * 8]);
        float4 xb = *reinterpret_cast<const float4*>(&xs[k * 64 + ty * 8 + 4]);
        ulonglong2 w0 = *reinterpret_cast<const ulonglong2*>(&Ws[k * 256 + tx * 4]);
        ulonglong2 w1 = *reinterpret_cast<const ulonglong2*>(&Ws[k * 256 + tx * 4 + 128]);
        unsigned long long xp[8];
        xp[0] = pack2(xa.x); xp[1] = pack2(xa.y); xp[2] = pack2(xa.z); xp[3] = pack2(xa.w);
        xp[4] = pack2(xb.x); xp[5] = pack2(xb.y); xp[6] = pack2(xb.z); xp[7] = pack2(xb.w);
        #pragma unroll
        for (int m = 0; m < 8; m++) {
            ffma2(acc[m][0], xp[m], w0.x);
            ffma2(acc[m][1], xp[m], w0.y);
            ffma2(acc[m][2], xp[m], w1.x);
            ffma2(acc[m][3], xp[m], w1.y);
        }
    }

    const float4 bv0 = *reinterpret_cast<const float4*>(bg + n0 + tx * 4);
    const float4 bv1 = *reinterpret_cast<const float4*>(bg + n0 + tx * 4 + 128);
    #pragma unroll
    for (int m = 0; m < 8; m++) {
        float* orow = &g_e[(size_t)(m0 + ty * 8 + m) * ND + n0 + tx * 4];
        float2 a0 = unpack2(acc[m][0]);
        float2 a1 = unpack2(acc[m][1]);
        float2 a2 = unpack2(acc[m][2]);
        float2 a3 = unpack2(acc[m][3]);
        float4 r0, r1;
        r0.x = tanh_fast(a0.x + bv0.x);
        r0.y = tanh_fast(a0.y + bv0.y);
        r0.z = tanh_fast(a1.x + bv0.z);
        r0.w = tanh_fast(a1.y + bv0.w);
        r1.x = tanh_fast(a2.x + bv1.x);
        r1.y = tanh_fast(a2.y + bv1.y);
        r1.z = tanh_fast(a3.x + bv1.z);
        r1.w = tanh_fast(a3.y + bv1.w);
        *reinterpret_cast<float4*>(orow) = r0;
        *reinterpret_cast<float4*>(orow + 128) = r1;
    }
}

// ---------------------------------------------------------------------------
// Kernel B (R1 version, verbatim — measured 173 us):
// sequential recurrence + LayerNorm + fused logits epilogue.
// One block per batch row. 128 threads x 4 contiguous d's in registers.
// e_t prefetched 3 steps ahead via cp.async ring (thread-private slots).
// One __syncthreads per step (parity-double-buffered cross-warp reduce).
// ---------------------------------------------------------------------------
__global__ __launch_bounds__(128, 2)
void recur_kernel(const float* __restrict__ gamma, const float* __restrict__ beta,
                  const float* __restrict__ Wout, const float* __restrict__ bout,
                  const float* __restrict__ csp, float* __restrict__ outp) {
    __shared__ float es[4][ND];                  // cp.async ring, 4 stages
    __shared__ __align__(16) float2 red[2][4];   // per-warp (sum, sumsq), parity-buffered
    const int tid = threadIdx.x;
    const int b = blockIdx.x;
    const int d0 = tid * 4;
    const int wid = tid >> 5;
    const int lane = tid & 31;

    const float scale = __fdividef(1.0f, 1.0f + __expf(-csp[0]));  // sigmoid
    const float4 g4 = *reinterpret_cast<const float4*>(gamma + d0);
    const float4 be4 = *reinterpret_cast<const float4*>(beta + d0);

    float s0 = 0.f, s1 = 0.f, s2 = 0.f, s3 = 0.f;
    float h0 = 0.f, h1 = 0.f, h2 = 0.f, h3 = 0.f;
    const float* eb = g_e + (size_t)b * NT * ND;

    unsigned sdst[4];
    #pragma unroll
    for (int st = 0; st < 4; st++)
        sdst[st] = (unsigned)__cvta_generic_to_shared(&es[st][d0]);

    #pragma unroll
    for (int t = 0; t < 3; t++) {
        asm volatile("cp.async.ca.shared.global [%0], [%1], 16;"
                     :: "r"(sdst[t]), "l"(eb + (size_t)t * ND + d0));
        asm volatile("cp.async.commit_group;");
    }

    for (int t = 0; t < NT; t++) {
        const int tp = t + 3;
        if (tp < NT)
            asm volatile("cp.async.ca.shared.global [%0], [%1], 16;"
                         :: "r"(sdst[tp & 3]), "l"(eb + (size_t)tp * ND + d0));
        asm volatile("cp.async.commit_group;");   // one group per iter, uniform count
        asm volatile("cp.async.wait_group 3;");   // stage t is now resident

        float4 e4 = *reinterpret_cast<const float4*>(&es[t & 3][d0]);
        s0 = tanh_fast(fmaf(scale, s0, e4.x) + h0);
        s1 = tanh_fast(fmaf(scale, s1, e4.y) + h1);
        s2 = tanh_fast(fmaf(scale, s2, e4.z) + h2);
        s3 = tanh_fast(fmaf(scale, s3, e4.w) + h3);

        float sum = (s0 + s1) + (s2 + s3);
        float ssq = fmaf(s0, s0, s1 * s1) + fmaf(s2, s2, s3 * s3);
        #pragma unroll
        for (int m = 16; m >= 1; m >>= 1) {
            sum += __shfl_xor_sync(0xffffffffu, sum, m);
            ssq += __shfl_xor_sync(0xffffffffu, ssq, m);
        }
        if (lane == 0) red[t & 1][wid] = make_float2(sum, ssq);
        __syncthreads();
        float4 ra = *reinterpret_cast<const float4*>(&red[t & 1][0]);
        float4 rb = *reinterpret_cast<const float4*>(&red[t & 1][2]);
        float tsum = (ra.x + ra.z) + (rb.x + rb.z);
        float tssq = (ra.y + ra.w) + (rb.y + rb.w);
        float mean = tsum * (1.0f / ND);
        float var = fmaf(mean, -mean, tssq * (1.0f / ND));
        float rs = rsqrtf(var + 1e-5f);
        h0 = fmaf((s0 - mean) * rs, g4.x, be4.x);
        h1 = fmaf((s1 - mean) * rs, g4.y, be4.y);
        h2 = fmaf((s2 - mean) * rs, g4.z, be4.z);
        h3 = fmaf((s3 - mean) * rs, g4.w, be4.w);
    }

    // ---- fused logits: out[b][o] = b_out[o] + sum_d h[d] * W_out[o][d] ----
    asm volatile("cp.async.wait_group 0;");
    __syncthreads();
    *reinterpret_cast<float4*>(&es[0][d0]) = make_float4(h0, h1, h2, h3);
    __syncthreads();

    float acc = bout[tid];  // blockDim == NO == 128, thread owns output o = tid
    const float4* wr = reinterpret_cast<const float4*>(Wout + (size_t)tid * ND);
    const float4* hv = reinterpret_cast<const float4*>(&es[0][0]);
    #pragma unroll 8
    for (int q = 0; q < ND / 4; q++) {
        float4 w = __ldg(&wr[q]);
        float4 h = hv[q];
        acc = fmaf(w.x, h.x, fmaf(w.y, h.y, fmaf(w.z, h.z, fmaf(w.w, h.w, acc))));
    }
    outp[b * NO + tid] = acc;
}

// ---------------------------------------------------------------------------
extern "C" void kernel_launch(void* const* d_in, const int* in_sizes, int n_in,
                              void* d_out, int out_size) {
    const float* x     = (const float*)d_in[0];
    const float* Win   = (const float*)d_in[1];
    const float* bin   = (const float*)d_in[2];
    const float* gamma = (const float*)d_in[3];
    const float* beta  = (const float*)d_in[4];
    const float* Wout  = (const float*)d_in[5];
    const float* bout  = (const float*)d_in[6];
    const float* cs    = (const float*)d_in[7];
    float* out = (float*)d_out;

    const int smem = (NI * 256 + NI * 64) * (int)sizeof(float);  // 81920 B
    cudaFuncSetAttribute(embed_kernel, cudaFuncAttributeMaxDynamicSharedMemorySize, smem);
    embed_kernel<<<(NB * NT / 64) * 2, 256, smem>>>(x, Win, bin);
    recur_kernel<<<NB, 128>>>(gamma, beta, Wout, bout, cs, out);
}